// round 14
// baseline (speedup 1.0000x reference)
#include <cuda_runtime.h>

// Fixed problem dims
#define NB 4
#define NQv 512
#define MMv 512
#define DDv 256
#define HHv 256

// Scratch (device globals: no allocations allowed)
__device__ float    g_q[NB * NQv * HHv];     // projected q, [b*NQ+n][h]
__device__ unsigned g_kTh[NB * HHv * MMv];   // projected k, transposed, packed half2(k,k)
__device__ float    g_sc[NB * NQv * MMv];    // raw scores [b][n][m]

__device__ __forceinline__ float fex2(float x) {
    float y; asm("ex2.approx.f32 %0, %1;" : "=f"(y) : "f"(x)); return y;
}
__device__ __forceinline__ unsigned long long pk2(float a, float b) {
    unsigned long long r; asm("mov.b64 %0, {%1, %2};" : "=l"(r) : "f"(a), "f"(b)); return r;
}
__device__ __forceinline__ void fma2(unsigned long long &d, unsigned long long a, unsigned long long b) {
    asm("fma.rn.f32x2 %0, %1, %2, %0;" : "+l"(d) : "l"(a), "l"(b));
}
__device__ __forceinline__ float2 up2(unsigned long long v) {
    float2 r; asm("mov.b64 {%0, %1}, %2;" : "=f"(r.x), "=f"(r.y) : "l"(v)); return r;
}
__device__ __forceinline__ unsigned packh2(float lo, float hi) {
    unsigned r; asm("cvt.rn.f16x2.f32 %0, %1, %2;" : "=r"(r) : "f"(hi), "f"(lo)); return r;
}
__device__ __forceinline__ unsigned hadd2(unsigned a, unsigned b) {
    unsigned r; asm("add.f16x2 %0, %1, %2;" : "=r"(r) : "r"(a), "r"(b)); return r;
}
__device__ __forceinline__ unsigned htanh2(unsigned a) {
    unsigned r; asm("tanh.approx.f16x2 %0, %1;" : "=r"(r) : "r"(a)); return r;
}
__device__ __forceinline__ unsigned hfma2(unsigned a, unsigned b, unsigned c) {
    unsigned r; asm("fma.rn.f16x2 %0, %1, %2, %3;" : "=r"(r) : "r"(a), "r"(b), "r"(c)); return r;
}
__device__ __forceinline__ void drain2(unsigned p, float &f0, float &f1) {
    unsigned short lo, hi; float a, b;
    asm("mov.b32 {%0, %1}, %2;" : "=h"(lo), "=h"(hi) : "r"(p));
    asm("cvt.f32.f16 %0, %1;" : "=f"(a) : "h"(lo));
    asm("cvt.f32.f16 %0, %1;" : "=f"(b) : "h"(hi));
    f0 += a; f1 += b;
}

// ---------------------------------------------------------------------------
// Projection GEMM, LDS-optimized: 256 blocks (128 q, 128 kT), 64x64 tile,
// 128 THREADS, 4-row x 8-col micro-tile.
// LDS per thread per k: 16B A + 32B B for 16 FMA2 = 3B/FMA2 (half of the
// 4x4/256thr config) -> crossbar time ~12us vs 22.6 measured before.
// Double-buffered global loads. k output packed half2(k,k).
// ---------------------------------------------------------------------------
__global__ __launch_bounds__(128) void proj_kernel(const float* __restrict__ query,
                                                   const float* __restrict__ key,
                                                   const float* __restrict__ Wq,
                                                   const float* __restrict__ Wk)
{
    __shared__ __align__(16) float As[16][68];
    __shared__ __align__(16) float Bs[16][64];

    int bid = blockIdx.x;
    int is_k = bid >> 7;
    int local = bid & 127;
    int row0 = (local >> 2) * 64;
    int col0 = (local & 3) * 64;
    const float* A = is_k ? key : query;
    const float* B = is_k ? Wk : Wq;

    int t = threadIdx.x;
    int tx = t & 7, ty = t >> 3;          // tx: 8 col-groups(x8), ty: 16 row-groups(x4)

    // A-tile load: 64 rows x 16 k; 128 thr -> each loads float4 (row = t&63,
    // k-offset = (t>>6)*8, covering 8 of 16 k per thread via one float4 + second below)
    int arow = t & 63, ah = t >> 6;       // ah: 0/1 -> k-offset 0/8
    // B-tile load: 16 rows x 64 cols; 128 thr -> each loads 2 float4 (8 cols)
    int bk = t >> 3, bh = t & 7;

    const float* Aptr = A + (row0 + arow) * DDv + ah * 8;
    const float* Bptr = B + bk * HHv + col0 + bh * 8;

    unsigned long long acc[4][4];
#pragma unroll
    for (int i = 0; i < 4; i++)
#pragma unroll
        for (int j = 0; j < 4; j++) acc[i][j] = 0ull;

    // Prefetch slab 0
    float4 a_n0 = *(const float4*)(Aptr);
    float4 a_n1 = *(const float4*)(Aptr + 4);
    float4 b_n0 = *(const float4*)(Bptr);
    float4 b_n1 = *(const float4*)(Bptr + 4);

    for (int k0 = 0; k0 < DDv; k0 += 16) {
        // stage A: thread covers k = ah*8 + [0,8) for its row
        As[ah * 8 + 0][arow] = a_n0.x;
        As[ah * 8 + 1][arow] = a_n0.y;
        As[ah * 8 + 2][arow] = a_n0.z;
        As[ah * 8 + 3][arow] = a_n0.w;
        As[ah * 8 + 4][arow] = a_n1.x;
        As[ah * 8 + 5][arow] = a_n1.y;
        As[ah * 8 + 6][arow] = a_n1.z;
        As[ah * 8 + 7][arow] = a_n1.w;
        *(float4*)&Bs[bk][bh * 8 + 0] = b_n0;
        *(float4*)&Bs[bk][bh * 8 + 4] = b_n1;
        __syncthreads();

        if (k0 + 16 < DDv) {
            a_n0 = *(const float4*)(Aptr + k0 + 16);
            a_n1 = *(const float4*)(Aptr + k0 + 20);
            b_n0 = *(const float4*)(Bptr + (k0 + 16) * HHv);
            b_n1 = *(const float4*)(Bptr + (k0 + 16) * HHv + 4);
        }

#pragma unroll
        for (int k = 0; k < 16; k++) {
            const unsigned long long* br = (const unsigned long long*)&Bs[k][tx * 8];
            unsigned long long b0 = br[0], b1 = br[1], b2 = br[2], b3 = br[3];
#pragma unroll
            for (int i = 0; i < 4; i++) {
                float a = As[k][ty * 4 + i];
                unsigned long long aa = pk2(a, a);
                fma2(acc[i][0], aa, b0);
                fma2(acc[i][1], aa, b1);
                fma2(acc[i][2], aa, b2);
                fma2(acc[i][3], aa, b3);
            }
        }
        __syncthreads();
    }

#pragma unroll
    for (int i = 0; i < 4; i++) {
        int row = row0 + ty * 4 + i;
        int col = col0 + tx * 8;
        float2 c0 = up2(acc[i][0]);
        float2 c1 = up2(acc[i][1]);
        float2 c2 = up2(acc[i][2]);
        float2 c3 = up2(acc[i][3]);
        if (!is_k) {
            *(float4*)(g_q + row * HHv + col)     = make_float4(c0.x, c0.y, c1.x, c1.y);
            *(float4*)(g_q + row * HHv + col + 4) = make_float4(c2.x, c2.y, c3.x, c3.y);
        } else {
            int bb = row >> 9, m = row & 511;
            unsigned* base = g_kTh + (bb * HHv) * MMv + m;
            base[(col + 0) * MMv] = packh2(c0.x, c0.x);
            base[(col + 1) * MMv] = packh2(c0.y, c0.y);
            base[(col + 2) * MMv] = packh2(c1.x, c1.x);
            base[(col + 3) * MMv] = packh2(c1.y, c1.y);
            base[(col + 4) * MMv] = packh2(c2.x, c2.x);
            base[(col + 5) * MMv] = packh2(c2.y, c2.y);
            base[(col + 6) * MMv] = packh2(c3.x, c3.x);
            base[(col + 7) * MMv] = packh2(c3.y, c3.y);
        }
    }
}

// ---------------------------------------------------------------------------
// Score kernel (R9/R12 body, frozen at MUFU element-rate floor):
// tile (8q x 128m), 128 threads, grid 1024.
// ---------------------------------------------------------------------------
__global__ __launch_bounds__(128) void score_kernel(const float* __restrict__ Wv)
{
    __shared__ __align__(16) uint4 qsh[HHv];
    __shared__ __align__(16) unsigned wsh[HHv];

    int t = threadIdx.x;
    int bid = blockIdx.x;
    int mc = bid & 3;
    int qc = (bid >> 2) & 63;
    int b = bid >> 8;
    int n0 = qc * 8;
    int m = mc * 128 + t;

    {
        const float* qb = g_q + (b * NQv + n0) * HHv + 2 * t;
        float2 r[8];
#pragma unroll
        for (int q = 0; q < 8; q++)
            r[q] = *(const float2*)(qb + q * HHv);
#pragma unroll
        for (int j = 0; j < 2; j++) {
            int h = 2 * t + j;
            float v0 = j ? r[0].y : r[0].x, v1 = j ? r[1].y : r[1].x;
            float v2 = j ? r[2].y : r[2].x, v3 = j ? r[3].y : r[3].x;
            float v4 = j ? r[4].y : r[4].x, v5 = j ? r[5].y : r[5].x;
            float v6 = j ? r[6].y : r[6].x, v7 = j ? r[7].y : r[7].x;
            qsh[h] = make_uint4(packh2(v0, v1), packh2(v2, v3),
                                packh2(v4, v5), packh2(v6, v7));
        }
        float2 wv = *(const float2*)(Wv + 2 * t);
        wsh[2 * t + 0] = packh2(wv.x, wv.x);
        wsh[2 * t + 1] = packh2(wv.y, wv.y);
    }
    __syncthreads();

    float facc[8];
#pragma unroll
    for (int q = 0; q < 8; q++) facc[q] = 0.f;

    const unsigned* kb = g_kTh + (b * HHv) * MMv + m;

    for (int h0 = 0; h0 < HHv; h0 += 8) {
        unsigned acc2[4] = {0u, 0u, 0u, 0u};
#pragma unroll
        for (int hh = 0; hh < 8; hh++) {
            int h = h0 + hh;
            unsigned kk2 = kb[h * MMv];
            uint4 qh = qsh[h];
            unsigned w2 = wsh[h];
            acc2[0] = hfma2(w2, htanh2(hadd2(qh.x, kk2)), acc2[0]);
            acc2[1] = hfma2(w2, htanh2(hadd2(qh.y, kk2)), acc2[1]);
            acc2[2] = hfma2(w2, htanh2(hadd2(qh.z, kk2)), acc2[2]);
            acc2[3] = hfma2(w2, htanh2(hadd2(qh.w, kk2)), acc2[3]);
        }
        drain2(acc2[0], facc[0], facc[1]);
        drain2(acc2[1], facc[2], facc[3]);
        drain2(acc2[2], facc[4], facc[5]);
        drain2(acc2[3], facc[6], facc[7]);
    }

#pragma unroll
    for (int q = 0; q < 8; q++)
        g_sc[(b * NQv + n0 + q) * MMv + m] = facc[q];
}

// ---------------------------------------------------------------------------
// Softmax + AV (R12-proven, frozen): 16q/block + v-split 2, grid 256.
// ---------------------------------------------------------------------------
__global__ __launch_bounds__(256) void softav_kernel(const float* __restrict__ value,
                                                     float* __restrict__ out)
{
    __shared__ __align__(16) float sc[16][MMv];
    __shared__ float inv_s[16];
    float2 (*ps)[16][64] = (float2(*)[16][64])sc;

    int t = threadIdx.x;
    int bid = blockIdx.x;
    int vh = bid & 1;
    int qc = (bid >> 1) & 31;
    int b = bid >> 6;
    int n0 = qc * 16;
    int w = t >> 5, lane = t & 31;

#pragma unroll
    for (int r = 0; r < 2; r++) {
        int row = 2 * w + r;
        const float* srow = g_sc + (b * NQv + n0 + row) * MMv;
        float vals[16];
        float vmax = -1e30f;
#pragma unroll
        for (int j = 0; j < 16; j++) {
            vals[j] = srow[lane + j * 32];
            vmax = fmaxf(vmax, vals[j]);
        }
#pragma unroll
        for (int o = 16; o > 0; o >>= 1)
            vmax = fmaxf(vmax, __shfl_xor_sync(0xffffffffu, vmax, o));
        float sum = 0.f;
#pragma unroll
        for (int j = 0; j < 16; j++) {
            float p = fex2((vals[j] - vmax) * 1.4426950408889634f);
            sc[row][lane + j * 32] = p;
            sum += p;
        }
#pragma unroll
        for (int o = 16; o > 0; o >>= 1)
            sum += __shfl_xor_sync(0xffffffffu, sum, o);
        if (lane == 0) inv_s[row] = 1.0f / sum;
    }
    __syncthreads();

    int mg = t >> 6;
    int vg = t & 63;
    const float* vbase = value + (b * MMv + mg * 128) * DDv + vh * 128 + vg * 2;
    unsigned long long acc[16];
#pragma unroll
    for (int q = 0; q < 16; q++) acc[q] = 0ull;

    for (int m4 = 0; m4 < 128; m4 += 4) {
        float2 v0 = *(const float2*)(vbase + (m4 + 0) * DDv);
        float2 v1 = *(const float2*)(vbase + (m4 + 1) * DDv);
        float2 v2 = *(const float2*)(vbase + (m4 + 2) * DDv);
        float2 v3 = *(const float2*)(vbase + (m4 + 3) * DDv);
        unsigned long long w0 = pk2(v0.x, v0.y);
        unsigned long long w1 = pk2(v1.x, v1.y);
        unsigned long long w2 = pk2(v2.x, v2.y);
        unsigned long long w3 = pk2(v3.x, v3.y);
        int mIdx = mg * 128 + m4;
#pragma unroll
        for (int q = 0; q < 16; q++) {
            float4 p = *(const float4*)&sc[q][mIdx];
            fma2(acc[q], pk2(p.x, p.x), w0);
            fma2(acc[q], pk2(p.y, p.y), w1);
            fma2(acc[q], pk2(p.z, p.z), w2);
            fma2(acc[q], pk2(p.w, p.w), w3);
        }
    }
    __syncthreads();
#pragma unroll
    for (int q = 0; q < 16; q++) ps[mg][q][vg] = up2(acc[q]);
    __syncthreads();

#pragma unroll
    for (int r = 0; r < 4; r++) {
        int p = t + r * 256;
        int q = p >> 6, v2i = p & 63;
        float2 s0 = ps[0][q][v2i];
        float2 s1 = ps[1][q][v2i];
        float2 s2 = ps[2][q][v2i];
        float2 s3 = ps[3][q][v2i];
        float iv = inv_s[q];
        ((float2*)out)[(b * NQv + n0 + q) * 128 + vh * 64 + v2i] =
            make_float2((s0.x + s1.x + s2.x + s3.x) * iv,
                        (s0.y + s1.y + s2.y + s3.y) * iv);
    }
}

extern "C" void kernel_launch(void* const* d_in, const int* in_sizes, int n_in,
                              void* d_out, int out_size)
{
    const float* query = (const float*)d_in[0];
    const float* key   = (const float*)d_in[1];
    const float* value = (const float*)d_in[2];
    const float* Wq    = (const float*)d_in[3];
    const float* Wk    = (const float*)d_in[4];
    const float* Wv    = (const float*)d_in[5];
    float* out = (float*)d_out;

    proj_kernel<<<256, 128>>>(query, key, Wq, Wk);
    score_kernel<<<1024, 128>>>(Wv);
    softav_kernel<<<256, 256>>>(value, out);
}

// round 15
// speedup vs baseline: 1.1178x; 1.1178x over previous
#include <cuda_runtime.h>

// Fixed problem dims
#define NB 4
#define NQv 512
#define MMv 512
#define DDv 256
#define HHv 256

// Scratch (device globals: no allocations allowed)
__device__ float    g_q[NB * NQv * HHv];     // projected q, [b*NQ+n][h]
__device__ unsigned g_kTh[NB * HHv * MMv];   // projected k, transposed, packed half2(k,k)
__device__ float    g_sc[NB * NQv * MMv];    // raw scores [b][n][m]

__device__ __forceinline__ float fex2(float x) {
    float y; asm("ex2.approx.f32 %0, %1;" : "=f"(y) : "f"(x)); return y;
}
__device__ __forceinline__ unsigned long long pk2(float a, float b) {
    unsigned long long r; asm("mov.b64 %0, {%1, %2};" : "=l"(r) : "f"(a), "f"(b)); return r;
}
__device__ __forceinline__ void fma2(unsigned long long &d, unsigned long long a, unsigned long long b) {
    asm("fma.rn.f32x2 %0, %1, %2, %0;" : "+l"(d) : "l"(a), "l"(b));
}
__device__ __forceinline__ float2 up2(unsigned long long v) {
    float2 r; asm("mov.b64 {%0, %1}, %2;" : "=f"(r.x), "=f"(r.y) : "l"(v)); return r;
}
__device__ __forceinline__ unsigned packh2(float lo, float hi) {
    unsigned r; asm("cvt.rn.f16x2.f32 %0, %1, %2;" : "=r"(r) : "f"(hi), "f"(lo)); return r;
}
__device__ __forceinline__ unsigned hadd2(unsigned a, unsigned b) {
    unsigned r; asm("add.f16x2 %0, %1, %2;" : "=r"(r) : "r"(a), "r"(b)); return r;
}
__device__ __forceinline__ unsigned htanh2(unsigned a) {
    unsigned r; asm("tanh.approx.f16x2 %0, %1;" : "=r"(r) : "r"(a)); return r;
}
__device__ __forceinline__ unsigned hfma2(unsigned a, unsigned b, unsigned c) {
    unsigned r; asm("fma.rn.f16x2 %0, %1, %2, %3;" : "=r"(r) : "r"(a), "r"(b), "r"(c)); return r;
}
__device__ __forceinline__ void drain2(unsigned p, float &f0, float &f1) {
    unsigned short lo, hi; float a, b;
    asm("mov.b32 {%0, %1}, %2;" : "=h"(lo), "=h"(hi) : "r"(p));
    asm("cvt.f32.f16 %0, %1;" : "=f"(a) : "h"(lo));
    asm("cvt.f32.f16 %0, %1;" : "=f"(b) : "h"(hi));
    f0 += a; f1 += b;
}
__device__ __forceinline__ float tf32r(float x) {
    unsigned u; asm("cvt.rna.tf32.f32 %0, %1;" : "=r"(u) : "f"(x));
    return __uint_as_float(u);
}
__device__ __forceinline__ void mma_tf32(float* c,
                                         unsigned a0, unsigned a1, unsigned a2, unsigned a3,
                                         unsigned b0, unsigned b1) {
    asm("mma.sync.aligned.m16n8k8.row.col.f32.tf32.tf32.f32 "
        "{%0,%1,%2,%3}, {%4,%5,%6,%7}, {%8,%9}, {%0,%1,%2,%3};"
        : "+f"(c[0]), "+f"(c[1]), "+f"(c[2]), "+f"(c[3])
        : "r"(a0), "r"(a1), "r"(a2), "r"(a3), "r"(b0), "r"(b1));
}

// ---------------------------------------------------------------------------
// Projection GEMM via split-tf32 tensor-core MMA (error ~1e-6, f32-equivalent):
// A = Ah + Al (tf32 split), W = Wh + Wl; q = Ah*Wh + Al*Wh + Ah*Wl.
// 256 blocks (128 q, 128 kT), 256 thr = 8 warps (2m x 4n), block tile 64x64,
// warp tile 32x16, m16n8k8 frags from padded smem (conflict-free).
// ---------------------------------------------------------------------------
__global__ __launch_bounds__(256) void proj_kernel(const float* __restrict__ query,
                                                   const float* __restrict__ key,
                                                   const float* __restrict__ Wq,
                                                   const float* __restrict__ Wk)
{
    __shared__ __align__(16) float Ah[64][20];   // [row][k in chunk], pad 4
    __shared__ __align__(16) float Al[64][20];
    __shared__ __align__(16) float Wh[16][72];   // [k in chunk][col], pad 8
    __shared__ __align__(16) float Wl[16][72];

    int bid = blockIdx.x;
    int is_k = bid >> 7;
    int local = bid & 127;
    int row0 = (local >> 2) * 64;
    int col0 = (local & 3) * 64;
    const float* A = is_k ? key : query;
    const float* B = is_k ? Wk : Wq;

    int t = threadIdx.x;
    int lane = t & 31, wid = t >> 5;
    int wm = wid & 1, wn = wid >> 1;   // 2 m-groups x 4 n-groups

    int arow = t >> 2, ac4 = t & 3;    // A staging: 64 rows x 4 float4
    int wrow = t >> 4, wc4 = t & 15;   // W staging: 16 rows x 16 float4

    const float* Ag = A + (row0 + arow) * DDv + ac4 * 4;
    const float* Wg = B + wrow * HHv + col0 + wc4 * 4;

    float cacc[2][2][4];
#pragma unroll
    for (int i = 0; i < 2; i++)
#pragma unroll
        for (int j = 0; j < 2; j++)
#pragma unroll
            for (int r = 0; r < 4; r++) cacc[i][j][r] = 0.f;

    for (int ch = 0; ch < 16; ch++) {
        // Stage + split chunk: A 64x16, W 16x64
        float4 av = *(const float4*)(Ag + ch * 16);
        float4 wv = *(const float4*)(Wg + ch * 16 * HHv);
        float4 ahv = make_float4(tf32r(av.x), tf32r(av.y), tf32r(av.z), tf32r(av.w));
        float4 alv = make_float4(av.x - ahv.x, av.y - ahv.y, av.z - ahv.z, av.w - ahv.w);
        float4 whv = make_float4(tf32r(wv.x), tf32r(wv.y), tf32r(wv.z), tf32r(wv.w));
        float4 wlv = make_float4(wv.x - whv.x, wv.y - whv.y, wv.z - whv.z, wv.w - whv.w);
        *(float4*)&Ah[arow][ac4 * 4] = ahv;
        *(float4*)&Al[arow][ac4 * 4] = alv;
        *(float4*)&Wh[wrow][wc4 * 4] = whv;
        *(float4*)&Wl[wrow][wc4 * 4] = wlv;
        __syncthreads();

#pragma unroll
        for (int kk = 0; kk < 16; kk += 8) {
            // A fragments (hi and lo) for 2 m-frags
            unsigned fah[2][4], fal[2][4];
#pragma unroll
            for (int mf = 0; mf < 2; mf++) {
                int r = wm * 32 + mf * 16 + (lane >> 2);
                int c = kk + (lane & 3);
                fah[mf][0] = __float_as_uint(Ah[r][c]);
                fah[mf][1] = __float_as_uint(Ah[r + 8][c]);
                fah[mf][2] = __float_as_uint(Ah[r][c + 4]);
                fah[mf][3] = __float_as_uint(Ah[r + 8][c + 4]);
                fal[mf][0] = __float_as_uint(Al[r][c]);
                fal[mf][1] = __float_as_uint(Al[r + 8][c]);
                fal[mf][2] = __float_as_uint(Al[r][c + 4]);
                fal[mf][3] = __float_as_uint(Al[r + 8][c + 4]);
            }
            // B fragments (hi and lo) for 2 n-frags
            unsigned fbh[2][2], fbl[2][2];
#pragma unroll
            for (int nf = 0; nf < 2; nf++) {
                int kr = kk + (lane & 3);
                int cn = wn * 16 + nf * 8 + (lane >> 2);
                fbh[nf][0] = __float_as_uint(Wh[kr][cn]);
                fbh[nf][1] = __float_as_uint(Wh[kr + 4][cn]);
                fbl[nf][0] = __float_as_uint(Wl[kr][cn]);
                fbl[nf][1] = __float_as_uint(Wl[kr + 4][cn]);
            }
#pragma unroll
            for (int mf = 0; mf < 2; mf++)
#pragma unroll
                for (int nf = 0; nf < 2; nf++) {
                    mma_tf32(cacc[mf][nf], fah[mf][0], fah[mf][1], fah[mf][2], fah[mf][3],
                             fbh[nf][0], fbh[nf][1]);
                    mma_tf32(cacc[mf][nf], fal[mf][0], fal[mf][1], fal[mf][2], fal[mf][3],
                             fbh[nf][0], fbh[nf][1]);
                    mma_tf32(cacc[mf][nf], fah[mf][0], fah[mf][1], fah[mf][2], fah[mf][3],
                             fbl[nf][0], fbl[nf][1]);
                }
        }
        __syncthreads();
    }

    // Epilogue. C layout per lane: c0=(r,c), c1=(r,c+1), c2=(r+8,c), c3=(r+8,c+1)
    // with r = frag_row + lane>>2, c = frag_col + 2*(lane&3).
#pragma unroll
    for (int mf = 0; mf < 2; mf++)
#pragma unroll
        for (int nf = 0; nf < 2; nf++) {
            int r = row0 + wm * 32 + mf * 16 + (lane >> 2);
            int c = col0 + wn * 16 + nf * 8 + (lane & 3) * 2;
            float* cc = cacc[mf][nf];
            if (!is_k) {
                *(float2*)(g_q + r * HHv + c)       = make_float2(cc[0], cc[1]);
                *(float2*)(g_q + (r + 8) * HHv + c) = make_float2(cc[2], cc[3]);
            } else {
                int bb = r >> 9, m = r & 511;   // r and r+8 stay in the same batch
                unsigned* base = g_kTh + (bb * HHv) * MMv + m;
                base[(c + 0) * MMv]     = packh2(cc[0], cc[0]);
                base[(c + 1) * MMv]     = packh2(cc[1], cc[1]);
                base[(c + 0) * MMv + 8] = packh2(cc[2], cc[2]);
                base[(c + 1) * MMv + 8] = packh2(cc[3], cc[3]);
            }
        }
}

// ---------------------------------------------------------------------------
// Score kernel (R9/R12 body, frozen at MUFU element-rate floor):
// tile (8q x 128m), 128 threads, grid 1024.
// ---------------------------------------------------------------------------
__global__ __launch_bounds__(128) void score_kernel(const float* __restrict__ Wv)
{
    __shared__ __align__(16) uint4 qsh[HHv];
    __shared__ __align__(16) unsigned wsh[HHv];

    int t = threadIdx.x;
    int bid = blockIdx.x;
    int mc = bid & 3;
    int qc = (bid >> 2) & 63;
    int b = bid >> 8;
    int n0 = qc * 8;
    int m = mc * 128 + t;

    {
        const float* qb = g_q + (b * NQv + n0) * HHv + 2 * t;
        float2 r[8];
#pragma unroll
        for (int q = 0; q < 8; q++)
            r[q] = *(const float2*)(qb + q * HHv);
#pragma unroll
        for (int j = 0; j < 2; j++) {
            int h = 2 * t + j;
            float v0 = j ? r[0].y : r[0].x, v1 = j ? r[1].y : r[1].x;
            float v2 = j ? r[2].y : r[2].x, v3 = j ? r[3].y : r[3].x;
            float v4 = j ? r[4].y : r[4].x, v5 = j ? r[5].y : r[5].x;
            float v6 = j ? r[6].y : r[6].x, v7 = j ? r[7].y : r[7].x;
            qsh[h] = make_uint4(packh2(v0, v1), packh2(v2, v3),
                                packh2(v4, v5), packh2(v6, v7));
        }
        float2 wv = *(const float2*)(Wv + 2 * t);
        wsh[2 * t + 0] = packh2(wv.x, wv.x);
        wsh[2 * t + 1] = packh2(wv.y, wv.y);
    }
    __syncthreads();

    float facc[8];
#pragma unroll
    for (int q = 0; q < 8; q++) facc[q] = 0.f;

    const unsigned* kb = g_kTh + (b * HHv) * MMv + m;

    for (int h0 = 0; h0 < HHv; h0 += 8) {
        unsigned acc2[4] = {0u, 0u, 0u, 0u};
#pragma unroll
        for (int hh = 0; hh < 8; hh++) {
            int h = h0 + hh;
            unsigned kk2 = kb[h * MMv];
            uint4 qh = qsh[h];
            unsigned w2 = wsh[h];
            acc2[0] = hfma2(w2, htanh2(hadd2(qh.x, kk2)), acc2[0]);
            acc2[1] = hfma2(w2, htanh2(hadd2(qh.y, kk2)), acc2[1]);
            acc2[2] = hfma2(w2, htanh2(hadd2(qh.z, kk2)), acc2[2]);
            acc2[3] = hfma2(w2, htanh2(hadd2(qh.w, kk2)), acc2[3]);
        }
        drain2(acc2[0], facc[0], facc[1]);
        drain2(acc2[1], facc[2], facc[3]);
        drain2(acc2[2], facc[4], facc[5]);
        drain2(acc2[3], facc[6], facc[7]);
    }

#pragma unroll
    for (int q = 0; q < 8; q++)
        g_sc[(b * NQv + n0 + q) * MMv + m] = facc[q];
}

// ---------------------------------------------------------------------------
// Softmax + AV (R12-proven, frozen): 16q/block + v-split 2, grid 256.
// ---------------------------------------------------------------------------
__global__ __launch_bounds__(256) void softav_kernel(const float* __restrict__ value,
                                                     float* __restrict__ out)
{
    __shared__ __align__(16) float sc[16][MMv];
    __shared__ float inv_s[16];
    float2 (*ps)[16][64] = (float2(*)[16][64])sc;

    int t = threadIdx.x;
    int bid = blockIdx.x;
    int vh = bid & 1;
    int qc = (bid >> 1) & 31;
    int b = bid >> 6;
    int n0 = qc * 16;
    int w = t >> 5, lane = t & 31;

#pragma unroll
    for (int r = 0; r < 2; r++) {
        int row = 2 * w + r;
        const float* srow = g_sc + (b * NQv + n0 + row) * MMv;
        float vals[16];
        float vmax = -1e30f;
#pragma unroll
        for (int j = 0; j < 16; j++) {
            vals[j] = srow[lane + j * 32];
            vmax = fmaxf(vmax, vals[j]);
        }
#pragma unroll
        for (int o = 16; o > 0; o >>= 1)
            vmax = fmaxf(vmax, __shfl_xor_sync(0xffffffffu, vmax, o));
        float sum = 0.f;
#pragma unroll
        for (int j = 0; j < 16; j++) {
            float p = fex2((vals[j] - vmax) * 1.4426950408889634f);
            sc[row][lane + j * 32] = p;
            sum += p;
        }
#pragma unroll
        for (int o = 16; o > 0; o >>= 1)
            sum += __shfl_xor_sync(0xffffffffu, sum, o);
        if (lane == 0) inv_s[row] = 1.0f / sum;
    }
    __syncthreads();

    int mg = t >> 6;
    int vg = t & 63;
    const float* vbase = value + (b * MMv + mg * 128) * DDv + vh * 128 + vg * 2;
    unsigned long long acc[16];
#pragma unroll
    for (int q = 0; q < 16; q++) acc[q] = 0ull;

    for (int m4 = 0; m4 < 128; m4 += 4) {
        float2 v0 = *(const float2*)(vbase + (m4 + 0) * DDv);
        float2 v1 = *(const float2*)(vbase + (m4 + 1) * DDv);
        float2 v2 = *(const float2*)(vbase + (m4 + 2) * DDv);
        float2 v3 = *(const float2*)(vbase + (m4 + 3) * DDv);
        unsigned long long w0 = pk2(v0.x, v0.y);
        unsigned long long w1 = pk2(v1.x, v1.y);
        unsigned long long w2 = pk2(v2.x, v2.y);
        unsigned long long w3 = pk2(v3.x, v3.y);
        int mIdx = mg * 128 + m4;
#pragma unroll
        for (int q = 0; q < 16; q++) {
            float4 p = *(const float4*)&sc[q][mIdx];
            fma2(acc[q], pk2(p.x, p.x), w0);
            fma2(acc[q], pk2(p.y, p.y), w1);
            fma2(acc[q], pk2(p.z, p.z), w2);
            fma2(acc[q], pk2(p.w, p.w), w3);
        }
    }
    __syncthreads();
#pragma unroll
    for (int q = 0; q < 16; q++) ps[mg][q][vg] = up2(acc[q]);
    __syncthreads();

#pragma unroll
    for (int r = 0; r < 4; r++) {
        int p = t + r * 256;
        int q = p >> 6, v2i = p & 63;
        float2 s0 = ps[0][q][v2i];
        float2 s1 = ps[1][q][v2i];
        float2 s2 = ps[2][q][v2i];
        float2 s3 = ps[3][q][v2i];
        float iv = inv_s[q];
        ((float2*)out)[(b * NQv + n0 + q) * 128 + vh * 64 + v2i] =
            make_float2((s0.x + s1.x + s2.x + s3.x) * iv,
                        (s0.y + s1.y + s2.y + s3.y) * iv);
    }
}

extern "C" void kernel_launch(void* const* d_in, const int* in_sizes, int n_in,
                              void* d_out, int out_size)
{
    const float* query = (const float*)d_in[0];
    const float* key   = (const float*)d_in[1];
    const float* value = (const float*)d_in[2];
    const float* Wq    = (const float*)d_in[3];
    const float* Wk    = (const float*)d_in[4];
    const float* Wv    = (const float*)d_in[5];
    float* out = (float*)d_out;

    proj_kernel<<<256, 256>>>(query, key, Wq, Wk);
    score_kernel<<<1024, 128>>>(Wv);
    softav_kernel<<<256, 256>>>(value, out);
}

// round 16
// speedup vs baseline: 1.1219x; 1.0037x over previous
#include <cuda_runtime.h>

// Fixed problem dims
#define NB 4
#define NQv 512
#define MMv 512
#define DDv 256
#define HHv 256

// Scratch (device globals: no allocations allowed)
__device__ float    g_q[NB * NQv * HHv];     // projected q, [b*NQ+n][h]
__device__ unsigned g_kTh[NB * HHv * MMv];   // projected k, transposed, packed half2(k,k)
__device__ float    g_sc[NB * NQv * MMv];    // raw scores [b][n][m]

__device__ __forceinline__ float fex2(float x) {
    float y; asm("ex2.approx.f32 %0, %1;" : "=f"(y) : "f"(x)); return y;
}
__device__ __forceinline__ unsigned long long pk2(float a, float b) {
    unsigned long long r; asm("mov.b64 %0, {%1, %2};" : "=l"(r) : "f"(a), "f"(b)); return r;
}
__device__ __forceinline__ void fma2(unsigned long long &d, unsigned long long a, unsigned long long b) {
    asm("fma.rn.f32x2 %0, %1, %2, %0;" : "+l"(d) : "l"(a), "l"(b));
}
__device__ __forceinline__ float2 up2(unsigned long long v) {
    float2 r; asm("mov.b64 {%0, %1}, %2;" : "=f"(r.x), "=f"(r.y) : "l"(v)); return r;
}
__device__ __forceinline__ unsigned packh2(float lo, float hi) {
    unsigned r; asm("cvt.rn.f16x2.f32 %0, %1, %2;" : "=r"(r) : "f"(hi), "f"(lo)); return r;
}
__device__ __forceinline__ unsigned hadd2(unsigned a, unsigned b) {
    unsigned r; asm("add.f16x2 %0, %1, %2;" : "=r"(r) : "r"(a), "r"(b)); return r;
}
__device__ __forceinline__ unsigned htanh2(unsigned a) {
    unsigned r; asm("tanh.approx.f16x2 %0, %1;" : "=r"(r) : "r"(a)); return r;
}
__device__ __forceinline__ unsigned hfma2(unsigned a, unsigned b, unsigned c) {
    unsigned r; asm("fma.rn.f16x2 %0, %1, %2, %3;" : "=r"(r) : "r"(a), "r"(b), "r"(c)); return r;
}
__device__ __forceinline__ void drain2(unsigned p, float &f0, float &f1) {
    unsigned short lo, hi; float a, b;
    asm("mov.b32 {%0, %1}, %2;" : "=h"(lo), "=h"(hi) : "r"(p));
    asm("cvt.f32.f16 %0, %1;" : "=f"(a) : "h"(lo));
    asm("cvt.f32.f16 %0, %1;" : "=f"(b) : "h"(hi));
    f0 += a; f1 += b;
}
__device__ __forceinline__ float tf32r(float x) {
    unsigned u; asm("cvt.rna.tf32.f32 %0, %1;" : "=r"(u) : "f"(x));
    return __uint_as_float(u);
}
__device__ __forceinline__ void mma_tf32(float* c,
                                         unsigned a0, unsigned a1, unsigned a2, unsigned a3,
                                         unsigned b0, unsigned b1) {
    asm("mma.sync.aligned.m16n8k8.row.col.f32.tf32.tf32.f32 "
        "{%0,%1,%2,%3}, {%4,%5,%6,%7}, {%8,%9}, {%0,%1,%2,%3};"
        : "+f"(c[0]), "+f"(c[1]), "+f"(c[2]), "+f"(c[3])
        : "r"(a0), "r"(a1), "r"(a2), "r"(a3), "r"(b0), "r"(b1));
}

// ---------------------------------------------------------------------------
// Projection GEMM via split-tf32 tensor-core MMA (f32-equivalent accuracy),
// now SOFTWARE-PIPELINED: chunk ch+1's global loads are issued right after
// the staging sync, flying under chunk ch's fragment-LDS + MMA work.
// 256 blocks (128 q, 128 kT), 256 thr = 8 warps (2m x 4n), block tile 64x64,
// warp tile 32x16, m16n8k8 frags from padded smem (conflict-free).
// ---------------------------------------------------------------------------
__global__ __launch_bounds__(256) void proj_kernel(const float* __restrict__ query,
                                                   const float* __restrict__ key,
                                                   const float* __restrict__ Wq,
                                                   const float* __restrict__ Wk)
{
    __shared__ __align__(16) float Ah[64][20];   // [row][k in chunk], pad 4
    __shared__ __align__(16) float Al[64][20];
    __shared__ __align__(16) float Wh[16][72];   // [k in chunk][col], pad 8
    __shared__ __align__(16) float Wl[16][72];

    int bid = blockIdx.x;
    int is_k = bid >> 7;
    int local = bid & 127;
    int row0 = (local >> 2) * 64;
    int col0 = (local & 3) * 64;
    const float* A = is_k ? key : query;
    const float* B = is_k ? Wk : Wq;

    int t = threadIdx.x;
    int lane = t & 31, wid = t >> 5;
    int wm = wid & 1, wn = wid >> 1;   // 2 m-groups x 4 n-groups

    int arow = t >> 2, ac4 = t & 3;    // A staging: 64 rows x 4 float4
    int wrow = t >> 4, wc4 = t & 15;   // W staging: 16 rows x 16 float4

    const float* Ag = A + (row0 + arow) * DDv + ac4 * 4;
    const float* Wg = B + wrow * HHv + col0 + wc4 * 4;

    float cacc[2][2][4];
#pragma unroll
    for (int i = 0; i < 2; i++)
#pragma unroll
        for (int j = 0; j < 2; j++)
#pragma unroll
            for (int r = 0; r < 4; r++) cacc[i][j][r] = 0.f;

    // Prefetch chunk 0
    float4 av = *(const float4*)(Ag);
    float4 wv = *(const float4*)(Wg);

    for (int ch = 0; ch < 16; ch++) {
        // Stage + split current chunk (A 64x16, W 16x64)
        float4 ahv = make_float4(tf32r(av.x), tf32r(av.y), tf32r(av.z), tf32r(av.w));
        float4 alv = make_float4(av.x - ahv.x, av.y - ahv.y, av.z - ahv.z, av.w - ahv.w);
        float4 whv = make_float4(tf32r(wv.x), tf32r(wv.y), tf32r(wv.z), tf32r(wv.w));
        float4 wlv = make_float4(wv.x - whv.x, wv.y - whv.y, wv.z - whv.z, wv.w - whv.w);
        *(float4*)&Ah[arow][ac4 * 4] = ahv;
        *(float4*)&Al[arow][ac4 * 4] = alv;
        *(float4*)&Wh[wrow][wc4 * 4] = whv;
        *(float4*)&Wl[wrow][wc4 * 4] = wlv;
        __syncthreads();

        // Issue next chunk's loads NOW — they fly under the MMA/LDS below.
        if (ch + 1 < 16) {
            av = *(const float4*)(Ag + (ch + 1) * 16);
            wv = *(const float4*)(Wg + (ch + 1) * 16 * HHv);
        }

#pragma unroll
        for (int kk = 0; kk < 16; kk += 8) {
            unsigned fah[2][4], fal[2][4];
#pragma unroll
            for (int mf = 0; mf < 2; mf++) {
                int r = wm * 32 + mf * 16 + (lane >> 2);
                int c = kk + (lane & 3);
                fah[mf][0] = __float_as_uint(Ah[r][c]);
                fah[mf][1] = __float_as_uint(Ah[r + 8][c]);
                fah[mf][2] = __float_as_uint(Ah[r][c + 4]);
                fah[mf][3] = __float_as_uint(Ah[r + 8][c + 4]);
                fal[mf][0] = __float_as_uint(Al[r][c]);
                fal[mf][1] = __float_as_uint(Al[r + 8][c]);
                fal[mf][2] = __float_as_uint(Al[r][c + 4]);
                fal[mf][3] = __float_as_uint(Al[r + 8][c + 4]);
            }
            unsigned fbh[2][2], fbl[2][2];
#pragma unroll
            for (int nf = 0; nf < 2; nf++) {
                int kr = kk + (lane & 3);
                int cn = wn * 16 + nf * 8 + (lane >> 2);
                fbh[nf][0] = __float_as_uint(Wh[kr][cn]);
                fbh[nf][1] = __float_as_uint(Wh[kr + 4][cn]);
                fbl[nf][0] = __float_as_uint(Wl[kr][cn]);
                fbl[nf][1] = __float_as_uint(Wl[kr + 4][cn]);
            }
#pragma unroll
            for (int mf = 0; mf < 2; mf++)
#pragma unroll
                for (int nf = 0; nf < 2; nf++) {
                    mma_tf32(cacc[mf][nf], fah[mf][0], fah[mf][1], fah[mf][2], fah[mf][3],
                             fbh[nf][0], fbh[nf][1]);
                    mma_tf32(cacc[mf][nf], fal[mf][0], fal[mf][1], fal[mf][2], fal[mf][3],
                             fbh[nf][0], fbh[nf][1]);
                    mma_tf32(cacc[mf][nf], fah[mf][0], fah[mf][1], fah[mf][2], fah[mf][3],
                             fbl[nf][0], fbl[nf][1]);
                }
        }
        __syncthreads();
    }

    // Epilogue. C layout per lane: c0=(r,c), c1=(r,c+1), c2=(r+8,c), c3=(r+8,c+1)
#pragma unroll
    for (int mf = 0; mf < 2; mf++)
#pragma unroll
        for (int nf = 0; nf < 2; nf++) {
            int r = row0 + wm * 32 + mf * 16 + (lane >> 2);
            int c = col0 + wn * 16 + nf * 8 + (lane & 3) * 2;
            float* cc = cacc[mf][nf];
            if (!is_k) {
                *(float2*)(g_q + r * HHv + c)       = make_float2(cc[0], cc[1]);
                *(float2*)(g_q + (r + 8) * HHv + c) = make_float2(cc[2], cc[3]);
            } else {
                int bb = r >> 9, m = r & 511;
                unsigned* base = g_kTh + (bb * HHv) * MMv + m;
                base[(c + 0) * MMv]     = packh2(cc[0], cc[0]);
                base[(c + 1) * MMv]     = packh2(cc[1], cc[1]);
                base[(c + 0) * MMv + 8] = packh2(cc[2], cc[2]);
                base[(c + 1) * MMv + 8] = packh2(cc[3], cc[3]);
            }
        }
}

// ---------------------------------------------------------------------------
// Score kernel (R9/R12 body, frozen at MUFU element-rate floor):
// tile (8q x 128m), 128 threads, grid 1024.
// ---------------------------------------------------------------------------
__global__ __launch_bounds__(128) void score_kernel(const float* __restrict__ Wv)
{
    __shared__ __align__(16) uint4 qsh[HHv];
    __shared__ __align__(16) unsigned wsh[HHv];

    int t = threadIdx.x;
    int bid = blockIdx.x;
    int mc = bid & 3;
    int qc = (bid >> 2) & 63;
    int b = bid >> 8;
    int n0 = qc * 8;
    int m = mc * 128 + t;

    {
        const float* qb = g_q + (b * NQv + n0) * HHv + 2 * t;
        float2 r[8];
#pragma unroll
        for (int q = 0; q < 8; q++)
            r[q] = *(const float2*)(qb + q * HHv);
#pragma unroll
        for (int j = 0; j < 2; j++) {
            int h = 2 * t + j;
            float v0 = j ? r[0].y : r[0].x, v1 = j ? r[1].y : r[1].x;
            float v2 = j ? r[2].y : r[2].x, v3 = j ? r[3].y : r[3].x;
            float v4 = j ? r[4].y : r[4].x, v5 = j ? r[5].y : r[5].x;
            float v6 = j ? r[6].y : r[6].x, v7 = j ? r[7].y : r[7].x;
            qsh[h] = make_uint4(packh2(v0, v1), packh2(v2, v3),
                                packh2(v4, v5), packh2(v6, v7));
        }
        float2 wv = *(const float2*)(Wv + 2 * t);
        wsh[2 * t + 0] = packh2(wv.x, wv.x);
        wsh[2 * t + 1] = packh2(wv.y, wv.y);
    }
    __syncthreads();

    float facc[8];
#pragma unroll
    for (int q = 0; q < 8; q++) facc[q] = 0.f;

    const unsigned* kb = g_kTh + (b * HHv) * MMv + m;

    for (int h0 = 0; h0 < HHv; h0 += 8) {
        unsigned acc2[4] = {0u, 0u, 0u, 0u};
#pragma unroll
        for (int hh = 0; hh < 8; hh++) {
            int h = h0 + hh;
            unsigned kk2 = kb[h * MMv];
            uint4 qh = qsh[h];
            unsigned w2 = wsh[h];
            acc2[0] = hfma2(w2, htanh2(hadd2(qh.x, kk2)), acc2[0]);
            acc2[1] = hfma2(w2, htanh2(hadd2(qh.y, kk2)), acc2[1]);
            acc2[2] = hfma2(w2, htanh2(hadd2(qh.z, kk2)), acc2[2]);
            acc2[3] = hfma2(w2, htanh2(hadd2(qh.w, kk2)), acc2[3]);
        }
        drain2(acc2[0], facc[0], facc[1]);
        drain2(acc2[1], facc[2], facc[3]);
        drain2(acc2[2], facc[4], facc[5]);
        drain2(acc2[3], facc[6], facc[7]);
    }

#pragma unroll
    for (int q = 0; q < 8; q++)
        g_sc[(b * NQv + n0 + q) * MMv + m] = facc[q];
}

// ---------------------------------------------------------------------------
// Softmax + AV (R12-proven, frozen): 16q/block + v-split 2, grid 256.
// ---------------------------------------------------------------------------
__global__ __launch_bounds__(256) void softav_kernel(const float* __restrict__ value,
                                                     float* __restrict__ out)
{
    __shared__ __align__(16) float sc[16][MMv];
    __shared__ float inv_s[16];
    float2 (*ps)[16][64] = (float2(*)[16][64])sc;

    int t = threadIdx.x;
    int bid = blockIdx.x;
    int vh = bid & 1;
    int qc = (bid >> 1) & 31;
    int b = bid >> 6;
    int n0 = qc * 16;
    int w = t >> 5, lane = t & 31;

#pragma unroll
    for (int r = 0; r < 2; r++) {
        int row = 2 * w + r;
        const float* srow = g_sc + (b * NQv + n0 + row) * MMv;
        float vals[16];
        float vmax = -1e30f;
#pragma unroll
        for (int j = 0; j < 16; j++) {
            vals[j] = srow[lane + j * 32];
            vmax = fmaxf(vmax, vals[j]);
        }
#pragma unroll
        for (int o = 16; o > 0; o >>= 1)
            vmax = fmaxf(vmax, __shfl_xor_sync(0xffffffffu, vmax, o));
        float sum = 0.f;
#pragma unroll
        for (int j = 0; j < 16; j++) {
            float p = fex2((vals[j] - vmax) * 1.4426950408889634f);
            sc[row][lane + j * 32] = p;
            sum += p;
        }
#pragma unroll
        for (int o = 16; o > 0; o >>= 1)
            sum += __shfl_xor_sync(0xffffffffu, sum, o);
        if (lane == 0) inv_s[row] = 1.0f / sum;
    }
    __syncthreads();

    int mg = t >> 6;
    int vg = t & 63;
    const float* vbase = value + (b * MMv + mg * 128) * DDv + vh * 128 + vg * 2;
    unsigned long long acc[16];
#pragma unroll
    for (int q = 0; q < 16; q++) acc[q] = 0ull;

    for (int m4 = 0; m4 < 128; m4 += 4) {
        float2 v0 = *(const float2*)(vbase + (m4 + 0) * DDv);
        float2 v1 = *(const float2*)(vbase + (m4 + 1) * DDv);
        float2 v2 = *(const float2*)(vbase + (m4 + 2) * DDv);
        float2 v3 = *(const float2*)(vbase + (m4 + 3) * DDv);
        unsigned long long w0 = pk2(v0.x, v0.y);
        unsigned long long w1 = pk2(v1.x, v1.y);
        unsigned long long w2 = pk2(v2.x, v2.y);
        unsigned long long w3 = pk2(v3.x, v3.y);
        int mIdx = mg * 128 + m4;
#pragma unroll
        for (int q = 0; q < 16; q++) {
            float4 p = *(const float4*)&sc[q][mIdx];
            fma2(acc[q], pk2(p.x, p.x), w0);
            fma2(acc[q], pk2(p.y, p.y), w1);
            fma2(acc[q], pk2(p.z, p.z), w2);
            fma2(acc[q], pk2(p.w, p.w), w3);
        }
    }
    __syncthreads();
#pragma unroll
    for (int q = 0; q < 16; q++) ps[mg][q][vg] = up2(acc[q]);
    __syncthreads();

#pragma unroll
    for (int r = 0; r < 4; r++) {
        int p = t + r * 256;
        int q = p >> 6, v2i = p & 63;
        float2 s0 = ps[0][q][v2i];
        float2 s1 = ps[1][q][v2i];
        float2 s2 = ps[2][q][v2i];
        float2 s3 = ps[3][q][v2i];
        float iv = inv_s[q];
        ((float2*)out)[(b * NQv + n0 + q) * 128 + vh * 64 + v2i] =
            make_float2((s0.x + s1.x + s2.x + s3.x) * iv,
                        (s0.y + s1.y + s2.y + s3.y) * iv);
    }
}

extern "C" void kernel_launch(void* const* d_in, const int* in_sizes, int n_in,
                              void* d_out, int out_size)
{
    const float* query = (const float*)d_in[0];
    const float* key   = (const float*)d_in[1];
    const float* value = (const float*)d_in[2];
    const float* Wq    = (const float*)d_in[3];
    const float* Wk    = (const float*)d_in[4];
    const float* Wv    = (const float*)d_in[5];
    float* out = (float*)d_out;

    proj_kernel<<<256, 256>>>(query, key, Wq, Wk);
    score_kernel<<<1024, 128>>>(Wv);
    softav_kernel<<<256, 256>>>(value, out);
}